// round 4
// baseline (speedup 1.0000x reference)
#include <cuda_runtime.h>
#include <cuda_bf16.h>

// MHC fused, grid=8192 work-stealing shape (harness-validated), restructured
// as streaming accumulation: mix/agg accumulate as each stream arrives
// (2-stream register pipeline), so post-barrier work is only out=mix+h*t.

#define NS        4
#define CDIM      4096
#define C4        (CDIM / 4)
#define THREADS   512
#define EPSF      1e-6f
#define SINKITERS 3

__global__ __launch_bounds__(THREADS, 2)
void mhc_stream_kernel(const float* __restrict__ x,
                       const float* __restrict__ w,
                       const float* __restrict__ Hpre,
                       const float* __restrict__ Hpost,
                       const float* __restrict__ Hres,
                       float* __restrict__ out)
{
    const int b   = blockIdx.x;
    const int tid = threadIdx.x;
    const int lane = tid & 31, wid = tid >> 5;

    const float4* __restrict__ xr =
        reinterpret_cast<const float4*>(x) + (size_t)b * (NS * C4);

    // ---- Issue loads for streams 0 and 1 immediately (evict-first) ----
    float4 cur0 = __ldcs(&xr[0 * C4 + tid]);
    float4 cur1 = __ldcs(&xr[0 * C4 + tid + THREADS]);
    float4 nxt0 = __ldcs(&xr[1 * C4 + tid]);
    float4 nxt1 = __ldcs(&xr[1 * C4 + tid + THREADS]);

    // ---- rmsnorm weight (L2-resident after first CTAs) ----
    const float4 wv0 = __ldg(reinterpret_cast<const float4*>(w) + tid);
    const float4 wv1 = __ldg(reinterpret_cast<const float4*>(w) + tid + THREADS);

    // ---- Tiny params: sigmoid gates + Sinkhorn (block-uniform) ----
    float hpre[NS], hpost[NS];
    #pragma unroll
    for (int i = 0; i < NS; i++) {
        hpre[i]  = 1.0f / (1.0f + expf(-Hpre[i]));
        hpost[i] = 2.0f / (1.0f + expf(-Hpost[i]));
    }
    float P[NS][NS];
    #pragma unroll
    for (int i = 0; i < NS; i++)
        #pragma unroll
        for (int j = 0; j < NS; j++)
            P[i][j] = expf(Hres[i * NS + j]);
    #pragma unroll
    for (int it = 0; it < SINKITERS; it++) {
        #pragma unroll
        for (int i = 0; i < NS; i++) {
            float ri = 1.0f / (P[i][0] + P[i][1] + P[i][2] + P[i][3] + EPSF);
            #pragma unroll
            for (int j = 0; j < NS; j++) P[i][j] *= ri;
        }
        #pragma unroll
        for (int j = 0; j < NS; j++) {
            float ci = 1.0f / (P[0][j] + P[1][j] + P[2][j] + P[3][j] + EPSF);
            #pragma unroll
            for (int i = 0; i < NS; i++) P[i][j] *= ci;
        }
    }

    // ---- Stream through the 4 streams, accumulating agg and mix ----
    float agg[8] = {0,0,0,0,0,0,0,0};
    float mix[NS][8];
    #pragma unroll
    for (int i = 0; i < NS; i++)
        #pragma unroll
        for (int e = 0; e < 8; e++) mix[i][e] = 0.0f;

    #pragma unroll
    for (int n = 0; n < NS; n++) {
        float xe[8] = {cur0.x, cur0.y, cur0.z, cur0.w,
                       cur1.x, cur1.y, cur1.z, cur1.w};
        // rotate pipeline: cur <- nxt, issue loads for stream n+2
        cur0 = nxt0; cur1 = nxt1;
        if (n + 2 < NS) {
            nxt0 = __ldcs(&xr[(n + 2) * C4 + tid]);
            nxt1 = __ldcs(&xr[(n + 2) * C4 + tid + THREADS]);
        }
        #pragma unroll
        for (int e = 0; e < 8; e++) {
            agg[e]    += hpre[n] * xe[e];
            mix[0][e] += P[0][n] * xe[e];
            mix[1][e] += P[1][n] * xe[e];
            mix[2][e] += P[2][n] * xe[e];
            mix[3][e] += P[3][n] * xe[e];
        }
    }

    // ---- bf16 round-trip + t = agg_bf * w, sum of squares ----
    const float wa[8] = {wv0.x, wv0.y, wv0.z, wv0.w,
                         wv1.x, wv1.y, wv1.z, wv1.w};
    float t[8];
    float ss = 0.0f;
    #pragma unroll
    for (int e = 0; e < 8; e++) {
        float a = __bfloat162float(__float2bfloat16_rn(agg[e]));
        ss += a * a;
        t[e] = a * wa[e];
    }

    // ---- Block reduction (512 thr = 16 warps, single barrier) ----
    #pragma unroll
    for (int o = 16; o > 0; o >>= 1)
        ss += __shfl_xor_sync(0xffffffffu, ss, o);
    __shared__ float wsum[THREADS / 32];
    if (lane == 0) wsum[wid] = ss;
    __syncthreads();
    float tot = 0.0f;
    #pragma unroll
    for (int i = 0; i < THREADS / 32; i++) tot += wsum[i];
    const float rinv = rsqrtf(tot * (1.0f / CDIM) + EPSF);

    // ---- out = mix + (hpost*rinv) * t ; short post-barrier path ----
    float4* __restrict__ orow =
        reinterpret_cast<float4*>(out) + (size_t)b * (NS * C4);
    #pragma unroll
    for (int i = 0; i < NS; i++) {
        const float h = hpost[i] * rinv;
        float4 o0, o1;
        o0.x = mix[i][0] + h * t[0];
        o0.y = mix[i][1] + h * t[1];
        o0.z = mix[i][2] + h * t[2];
        o0.w = mix[i][3] + h * t[3];
        o1.x = mix[i][4] + h * t[4];
        o1.y = mix[i][5] + h * t[5];
        o1.z = mix[i][6] + h * t[6];
        o1.w = mix[i][7] + h * t[7];
        orow[i * C4 + tid]           = o0;
        orow[i * C4 + tid + THREADS] = o1;
    }
}

extern "C" void kernel_launch(void* const* d_in, const int* in_sizes, int n_in,
                              void* d_out, int out_size)
{
    const float* x      = (const float*)d_in[0];
    const float* w      = (const float*)d_in[1];
    const float* H_pre  = (const float*)d_in[2];
    const float* H_post = (const float*)d_in[3];
    const float* H_res  = (const float*)d_in[4];
    float* out          = (float*)d_out;

    const int B = in_sizes[0] / (NS * CDIM);
    mhc_stream_kernel<<<B, THREADS>>>(x, w, H_pre, H_post, H_res, out);
}

// round 6
// speedup vs baseline: 1.3857x; 1.3857x over previous
#include <cuda_runtime.h>
#include <cuda_bf16.h>

// MHC fused, R1 skeleton (grid=8192, 512thr, front-batched 8x LDG.128) with:
//  - params (sigmoid gates + Sinkhorn) computed ONCE per block by warp 0,
//    broadcast via smem (extra barrier hidden under the in-flight LDGs)
//  - __ldcs on x (read-once), __stcs on out (never re-read)
//  - P / hpost smem reads deferred past the reduce barrier (reg pressure)

#define NS        4
#define CDIM      4096
#define C4        (CDIM / 4)
#define THREADS   512
#define EPSF      1e-6f
#define SINKITERS 3

// ps layout: [0..3]=sigmoid(H_pre), [4..7]=2*sigmoid(H_post), [8..23]=P row-major
__global__ __launch_bounds__(THREADS, 2)
void mhc_r5_kernel(const float* __restrict__ x,
                   const float* __restrict__ w,
                   const float* __restrict__ Hpre,
                   const float* __restrict__ Hpost,
                   const float* __restrict__ Hres,
                   float* __restrict__ out)
{
    const int b    = blockIdx.x;
    const int tid  = threadIdx.x;
    const int lane = tid & 31, wid = tid >> 5;

    // ---- Front-batched loads: 8x LDG.128, evict-first ----
    const float4* __restrict__ xr =
        reinterpret_cast<const float4*>(x) + (size_t)b * (NS * C4);
    float4 v4[NS][2];
    #pragma unroll
    for (int n = 0; n < NS; n++) {
        v4[n][0] = __ldcs(&xr[n * C4 + tid]);
        v4[n][1] = __ldcs(&xr[n * C4 + tid + THREADS]);
    }
    const float4 wv0 = __ldg(reinterpret_cast<const float4*>(w) + tid);
    const float4 wv1 = __ldg(reinterpret_cast<const float4*>(w) + tid + THREADS);

    // ---- Warp 0 computes tiny params once; smem broadcast ----
    __shared__ float ps[24];
    __shared__ float wsum[THREADS / 32];
    if (wid == 0) {
        float hpre[NS], hpost[NS], P[NS][NS];
        #pragma unroll
        for (int i = 0; i < NS; i++) {
            hpre[i]  = 1.0f / (1.0f + expf(-Hpre[i]));
            hpost[i] = 2.0f / (1.0f + expf(-Hpost[i]));
        }
        #pragma unroll
        for (int i = 0; i < NS; i++)
            #pragma unroll
            for (int j = 0; j < NS; j++)
                P[i][j] = expf(Hres[i * NS + j]);
        #pragma unroll
        for (int it = 0; it < SINKITERS; it++) {
            #pragma unroll
            for (int i = 0; i < NS; i++) {
                float ri = 1.0f / (P[i][0] + P[i][1] + P[i][2] + P[i][3] + EPSF);
                #pragma unroll
                for (int j = 0; j < NS; j++) P[i][j] *= ri;
            }
            #pragma unroll
            for (int j = 0; j < NS; j++) {
                float ci = 1.0f / (P[0][j] + P[1][j] + P[2][j] + P[3][j] + EPSF);
                #pragma unroll
                for (int i = 0; i < NS; i++) P[i][j] *= ci;
            }
        }
        if (lane == 0) {
            #pragma unroll
            for (int i = 0; i < NS; i++) { ps[i] = hpre[i]; ps[4 + i] = hpost[i]; }
            #pragma unroll
            for (int i = 0; i < NS; i++)
                #pragma unroll
                for (int j = 0; j < NS; j++)
                    ps[8 + i * NS + j] = P[i][j];
        }
    }
    __syncthreads();   // params ready; x LDGs still in flight underneath

    // ---- Unpack x into scalar regs ----
    float va[NS][8];
    #pragma unroll
    for (int n = 0; n < NS; n++) {
        va[n][0] = v4[n][0].x; va[n][1] = v4[n][0].y;
        va[n][2] = v4[n][0].z; va[n][3] = v4[n][0].w;
        va[n][4] = v4[n][1].x; va[n][5] = v4[n][1].y;
        va[n][6] = v4[n][1].z; va[n][7] = v4[n][1].w;
    }

    // ---- agg = sum_n hpre[n]*x[n]; bf16 round-trip; sum of squares ----
    const float h0 = ps[0], h1 = ps[1], h2 = ps[2], h3 = ps[3];
    float agg[8];
    float ss = 0.0f;
    #pragma unroll
    for (int e = 0; e < 8; e++) {
        float a = h0 * va[0][e] + h1 * va[1][e] + h2 * va[2][e] + h3 * va[3][e];
        a = __bfloat162float(__float2bfloat16_rn(a));
        agg[e] = a;
        ss += a * a;
    }

    // ---- Block reduction ----
    #pragma unroll
    for (int o = 16; o > 0; o >>= 1)
        ss += __shfl_xor_sync(0xffffffffu, ss, o);
    if (lane == 0) wsum[wid] = ss;
    __syncthreads();
    float tot = 0.0f;
    #pragma unroll
    for (int i = 0; i < THREADS / 32; i++) tot += wsum[i];
    const float rinv = rsqrtf(tot * (1.0f / CDIM) + EPSF);

    // ---- t = agg_bf * w ----
    const float wa[8] = {wv0.x, wv0.y, wv0.z, wv0.w,
                         wv1.x, wv1.y, wv1.z, wv1.w};
    float t[8];
    #pragma unroll
    for (int e = 0; e < 8; e++) t[e] = agg[e] * wa[e];

    // ---- Mix (P, hpost pulled from smem here, post-barrier) + stores ----
    float4* __restrict__ orow =
        reinterpret_cast<float4*>(out) + (size_t)b * (NS * C4);
    #pragma unroll
    for (int i = 0; i < NS; i++) {
        const float p0 = ps[8 + i * NS + 0], p1 = ps[8 + i * NS + 1];
        const float p2 = ps[8 + i * NS + 2], p3 = ps[8 + i * NS + 3];
        const float h  = ps[4 + i] * rinv;
        float o[8];
        #pragma unroll
        for (int e = 0; e < 8; e++) {
            o[e] = p0 * va[0][e] + p1 * va[1][e]
                 + p2 * va[2][e] + p3 * va[3][e]
                 + h * t[e];
        }
        __stcs(&orow[i * C4 + tid],
               make_float4(o[0], o[1], o[2], o[3]));
        __stcs(&orow[i * C4 + tid + THREADS],
               make_float4(o[4], o[5], o[6], o[7]));
    }
}

extern "C" void kernel_launch(void* const* d_in, const int* in_sizes, int n_in,
                              void* d_out, int out_size)
{
    const float* x      = (const float*)d_in[0];
    const float* w      = (const float*)d_in[1];
    const float* H_pre  = (const float*)d_in[2];
    const float* H_post = (const float*)d_in[3];
    const float* H_res  = (const float*)d_in[4];
    float* out          = (float*)d_out;

    const int B = in_sizes[0] / (NS * CDIM);
    mhc_r5_kernel<<<B, THREADS>>>(x, w, H_pre, H_post, H_res, out);
}

// round 7
// speedup vs baseline: 1.4597x; 1.0534x over previous
#include <cuda_runtime.h>
#include <cuda_bf16.h>
#include <cstdint>

// MHC fused: persistent work-stealing + L2-prefetch pipeline.
// grid = #SMs, 1 CTA/SM, 512 threads. Rows distributed via a global atomic
// ticket (self-resetting, graph-replay safe). Each iteration prefetches the
// NEXT row into L2 (1 cache line per thread) so DRAM reads run a full row
// ahead of the registers; current-row LDGs mostly hit L2.

#define NS        4
#define CDIM      4096
#define C4        (CDIM / 4)
#define THREADS   512
#define NWARPS    (THREADS / 32)
#define EPSF      1e-6f
#define SINKITERS 3
#define ROW_BYTES (NS * CDIM * 4)   // 65536 = 512 threads * 128B

__device__ int g_ticket = 0;
__device__ int g_done   = 0;

__device__ __forceinline__ void pf_l2(const void* p) {
    asm volatile("prefetch.global.L2 [%0];" :: "l"(p));
}

__global__ __launch_bounds__(THREADS, 1)
void mhc_ws_kernel(const float* __restrict__ x,
                   const float* __restrict__ w,
                   const float* __restrict__ Hpre,
                   const float* __restrict__ Hpost,
                   const float* __restrict__ Hres,
                   float* __restrict__ out, int B)
{
    __shared__ float ps[24];                 // hpre[4], hpost[4], P[16]
    __shared__ float wsum[2][NWARPS];
    __shared__ int   nrow[2];

    const int tid = threadIdx.x, lane = tid & 31, wid = tid >> 5;

    // ---- Warp 0: tiny params once (sigmoids + Sinkhorn) -> smem ----
    if (wid == 0) {
        float hpre[NS], hpost[NS], P[NS][NS];
        #pragma unroll
        for (int i = 0; i < NS; i++) {
            hpre[i]  = 1.0f / (1.0f + expf(-Hpre[i]));
            hpost[i] = 2.0f / (1.0f + expf(-Hpost[i]));
        }
        #pragma unroll
        for (int i = 0; i < NS; i++)
            #pragma unroll
            for (int j = 0; j < NS; j++)
                P[i][j] = expf(Hres[i * NS + j]);
        #pragma unroll
        for (int it = 0; it < SINKITERS; it++) {
            #pragma unroll
            for (int i = 0; i < NS; i++) {
                float ri = 1.0f / (P[i][0] + P[i][1] + P[i][2] + P[i][3] + EPSF);
                #pragma unroll
                for (int j = 0; j < NS; j++) P[i][j] *= ri;
            }
            #pragma unroll
            for (int j = 0; j < NS; j++) {
                float ci = 1.0f / (P[0][j] + P[1][j] + P[2][j] + P[3][j] + EPSF);
                #pragma unroll
                for (int i = 0; i < NS; i++) P[i][j] *= ci;
            }
        }
        if (lane == 0) {
            #pragma unroll
            for (int i = 0; i < NS; i++) { ps[i] = hpre[i]; ps[4 + i] = hpost[i]; }
            #pragma unroll
            for (int i = 0; i < NS; i++)
                #pragma unroll
                for (int j = 0; j < NS; j++)
                    ps[8 + i * NS + j] = P[i][j];
        }
    }

    // ---- Grab first two rows ----
    if (tid == 0) {
        nrow[0] = atomicAdd(&g_ticket, 1);
        nrow[1] = atomicAdd(&g_ticket, 1);
    }
    __syncthreads();

    // Loop-invariant params into registers (1 CTA/SM: regs are plentiful)
    const float h0 = ps[0], h1 = ps[1], h2 = ps[2], h3 = ps[3];
    float Pr[NS][NS], hp[NS];
    #pragma unroll
    for (int i = 0; i < NS; i++) {
        hp[i] = ps[4 + i];
        #pragma unroll
        for (int j = 0; j < NS; j++) Pr[i][j] = ps[8 + i * NS + j];
    }
    const float4 wv0 = __ldg(reinterpret_cast<const float4*>(w) + tid);
    const float4 wv1 = __ldg(reinterpret_cast<const float4*>(w) + tid + THREADS);
    const float wa[8] = {wv0.x, wv0.y, wv0.z, wv0.w,
                         wv1.x, wv1.y, wv1.z, wv1.w};

    const char* __restrict__ xb = reinterpret_cast<const char*>(x);
    int cur = nrow[0], nxt = nrow[1];
    int k = 0;

    while (cur < B) {
        // ---- Prefetch NEXT row into L2 (one 128B line per thread) ----
        if (nxt < B)
            pf_l2(xb + (size_t)nxt * ROW_BYTES + tid * 128);

        // ---- Front-batched loads of current row (L2 hits), evict-first ----
        const float4* __restrict__ xr =
            reinterpret_cast<const float4*>(xb + (size_t)cur * ROW_BYTES);
        float4 v4[NS][2];
        #pragma unroll
        for (int n = 0; n < NS; n++) {
            v4[n][0] = __ldcs(&xr[n * C4 + tid]);
            v4[n][1] = __ldcs(&xr[n * C4 + tid + THREADS]);
        }

        // ---- Grab row after next (published at this iteration's barrier) ----
        if (tid == 0) nrow[k & 1] = atomicAdd(&g_ticket, 1);

        // ---- Unpack ----
        float va[NS][8];
        #pragma unroll
        for (int n = 0; n < NS; n++) {
            va[n][0] = v4[n][0].x; va[n][1] = v4[n][0].y;
            va[n][2] = v4[n][0].z; va[n][3] = v4[n][0].w;
            va[n][4] = v4[n][1].x; va[n][5] = v4[n][1].y;
            va[n][6] = v4[n][1].z; va[n][7] = v4[n][1].w;
        }

        // ---- agg + bf16 round-trip + sum of squares ----
        float agg[8];
        float ss = 0.0f;
        #pragma unroll
        for (int e = 0; e < 8; e++) {
            float a = h0 * va[0][e] + h1 * va[1][e]
                    + h2 * va[2][e] + h3 * va[3][e];
            a = __bfloat162float(__float2bfloat16_rn(a));
            agg[e] = a;
            ss += a * a;
        }

        // ---- Block reduce (single barrier, parity slots) ----
        #pragma unroll
        for (int o = 16; o > 0; o >>= 1)
            ss += __shfl_xor_sync(0xffffffffu, ss, o);
        if (lane == 0) wsum[k & 1][wid] = ss;
        __syncthreads();
        float tot = 0.0f;
        #pragma unroll
        for (int i = 0; i < NWARPS; i++) tot += wsum[k & 1][i];
        const float rinv = rsqrtf(tot * (1.0f / CDIM) + EPSF);
        const int nn = nrow[k & 1];

        // ---- t = agg_bf * w ; mix + stores (streaming) ----
        float t[8];
        #pragma unroll
        for (int e = 0; e < 8; e++) t[e] = agg[e] * wa[e];

        float4* __restrict__ orow =
            reinterpret_cast<float4*>(out) + (size_t)cur * (NS * C4);
        #pragma unroll
        for (int i = 0; i < NS; i++) {
            const float h = hp[i] * rinv;
            float o[8];
            #pragma unroll
            for (int e = 0; e < 8; e++) {
                o[e] = Pr[i][0] * va[0][e] + Pr[i][1] * va[1][e]
                     + Pr[i][2] * va[2][e] + Pr[i][3] * va[3][e]
                     + h * t[e];
            }
            __stcs(&orow[i * C4 + tid],
                   make_float4(o[0], o[1], o[2], o[3]));
            __stcs(&orow[i * C4 + tid + THREADS],
                   make_float4(o[4], o[5], o[6], o[7]));
        }

        cur = nxt; nxt = nn; k++;
    }

    // ---- Self-reset for graph replay: last CTA zeroes the counters ----
    if (tid == 0) {
        int d = atomicAdd(&g_done, 1);
        if (d == (int)gridDim.x - 1) {
            g_ticket = 0;
            g_done   = 0;
        }
    }
}

extern "C" void kernel_launch(void* const* d_in, const int* in_sizes, int n_in,
                              void* d_out, int out_size)
{
    const float* x      = (const float*)d_in[0];
    const float* w      = (const float*)d_in[1];
    const float* H_pre  = (const float*)d_in[2];
    const float* H_post = (const float*)d_in[3];
    const float* H_res  = (const float*)d_in[4];
    float* out          = (float*)d_out;

    const int B = in_sizes[0] / (NS * CDIM);

    int dev = 0, nsm = 148;
    cudaGetDevice(&dev);
    cudaDeviceGetAttribute(&nsm, cudaDevAttrMultiProcessorCount, dev);

    mhc_ws_kernel<<<nsm, THREADS>>>(x, w, H_pre, H_post, H_res, out, B);
}